// round 9
// baseline (speedup 1.0000x reference)
#include <cuda_runtime.h>
#include <cuda_bf16.h>
#include <math.h>

// total = sum_i [ 0.5*(w^2 - ((w-mu)/sig)^2) - log(sig) ]   (weights)
//       + sum_j [ 0.5*((y-mup)/sp)^2 ]                       (likelihood, negated)
//       + B * (log(sp) + HALF_LOG_2PI)                       (closed-form constant)
//
// Hybrid schedule: first S indexes (72%) via fully-pipelined static grid-stride;
// last 28% via warp-level chunk stealing to absorb between-SM speed spread.
// All partials converted to int64 fixed-point -> order-independent, deterministic.

#define HALF_LOG_2PI 0.9189385332046727
#define LN2F 0.6931471805599453f

static constexpr int    BLOCKS  = 296;   // 148 SMs x 2 resident blocks, single wave
static constexpr int    THREADS = 256;
static constexpr double FXSCALE = 4194304.0;   // 2^22

__device__ long long    g_sum    = 0;
__device__ unsigned int g_ticket = 0;
__device__ unsigned int g_done   = 0;

__device__ __forceinline__ float frcp_fast(float x) {
    float r;
    asm("rcp.approx.ftz.f32 %0, %1;" : "=f"(r) : "f"(x));
    return r;
}

__device__ __forceinline__ float4 ldcs_pf(const float4* p) {
    float4 v;
    asm volatile("ld.global.cs.L2::256B.v4.f32 {%0,%1,%2,%3}, [%4];"
                 : "=f"(v.x), "=f"(v.y), "=f"(v.z), "=f"(v.w) : "l"(p));
    return v;
}

__device__ __forceinline__ float quad(const float4& a, const float4& b,
                                      const float4& c, const float4& d,
                                      const float4& e, float inv_sp) {
    float zx = (a.x - b.x) * frcp_fast(c.x);
    float zy = (a.y - b.y) * frcp_fast(c.y);
    float zz = (a.z - b.z) * frcp_fast(c.z);
    float zw = (a.w - b.w) * frcp_fast(c.w);
    float ux = (e.x - d.x) * inv_sp;
    float uy = (e.y - d.y) * inv_sp;
    float uz = (e.z - d.z) * inv_sp;
    float uw = (e.w - d.w) * inv_sp;

    float sq = (a.x * a.x - zx * zx) + (a.y * a.y - zy * zy)
             + (a.z * a.z - zz * zz) + (a.w * a.w - zw * zw)
             + (ux * ux + uy * uy) + (uz * uz + uw * uw);

    float prod = (c.x * c.y) * (c.z * c.w);   // grouped log: 1 MUFU per 4 sigmas
    return 0.5f * sq - LN2F * __log2f(prod);
}

__global__ __launch_bounds__(THREADS, 2)
void fused_loss_kernel(const float4* __restrict__ w,
                       const float4* __restrict__ mu,
                       const float4* __restrict__ sg,
                       const float4* __restrict__ mp,
                       const float4* __restrict__ yt,
                       const float*  __restrict__ sp_ptr,
                       float* __restrict__ out,
                       int S, int nchunks, int n_batch) {
    const float inv_sp = frcp_fast(*sp_ptr);
    const int stride  = gridDim.x * blockDim.x;
    const int stride4 = stride * 4;
    const int lane    = threadIdx.x & 31;

    // ---- static region [0, S): fully pipelined, 4x unroll, 20 LDG front-batched
    float acc0 = 0.0f, acc1 = 0.0f, acc2 = 0.0f, acc3 = 0.0f;
    int i = blockIdx.x * blockDim.x + threadIdx.x;
    for (; i + 3 * stride < S; i += stride4) {
        int i1 = i + stride, i2 = i + 2 * stride, i3 = i + 3 * stride;
        float4 a0 = ldcs_pf(&w[i]),  b0 = ldcs_pf(&mu[i]),  c0 = ldcs_pf(&sg[i]),
               d0 = ldcs_pf(&mp[i]), e0 = ldcs_pf(&yt[i]);
        float4 a1 = ldcs_pf(&w[i1]), b1 = ldcs_pf(&mu[i1]), c1 = ldcs_pf(&sg[i1]),
               d1 = ldcs_pf(&mp[i1]), e1 = ldcs_pf(&yt[i1]);
        float4 a2 = ldcs_pf(&w[i2]), b2 = ldcs_pf(&mu[i2]), c2 = ldcs_pf(&sg[i2]),
               d2 = ldcs_pf(&mp[i2]), e2 = ldcs_pf(&yt[i2]);
        float4 a3 = ldcs_pf(&w[i3]), b3 = ldcs_pf(&mu[i3]), c3 = ldcs_pf(&sg[i3]),
               d3 = ldcs_pf(&mp[i3]), e3 = ldcs_pf(&yt[i3]);
        acc0 += quad(a0, b0, c0, d0, e0, inv_sp);
        acc1 += quad(a1, b1, c1, d1, e1, inv_sp);
        acc2 += quad(a2, b2, c2, d2, e2, inv_sp);
        acc3 += quad(a3, b3, c3, d3, e3, inv_sp);
    }
    for (; i < S; i += stride) {
        float4 a = ldcs_pf(&w[i]), b = ldcs_pf(&mu[i]), c = ldcs_pf(&sg[i]),
               d = ldcs_pf(&mp[i]), e = ldcs_pf(&yt[i]);
        acc0 += quad(a, b, c, d, e, inv_sp);
    }

    // static partial is schedule-independent -> convert once
    long long accfx =
        __double2ll_rn((double)((acc0 + acc1) + (acc2 + acc3)) * FXSCALE);

    // ---- dynamic tail [S, S + nchunks*128): warp-level chunk stealing
    unsigned c = 0;
    if (lane == 0) c = atomicAdd(&g_ticket, 1u);
    c = __shfl_sync(0xFFFFFFFFu, c, 0);
    while (c < (unsigned)nchunks) {
        unsigned cn = 0;
        if (lane == 0) cn = atomicAdd(&g_ticket, 1u);   // prefetch next ticket

        int j0 = S + ((int)c << 7) + lane;
        int j1 = j0 + 32, j2 = j0 + 64, j3 = j0 + 96;
        float4 a0 = ldcs_pf(&w[j0]),  b0 = ldcs_pf(&mu[j0]),  c0 = ldcs_pf(&sg[j0]),
               d0 = ldcs_pf(&mp[j0]), e0 = ldcs_pf(&yt[j0]);
        float4 a1 = ldcs_pf(&w[j1]),  b1 = ldcs_pf(&mu[j1]),  c1 = ldcs_pf(&sg[j1]),
               d1 = ldcs_pf(&mp[j1]), e1 = ldcs_pf(&yt[j1]);
        float4 a2 = ldcs_pf(&w[j2]),  b2 = ldcs_pf(&mu[j2]),  c2 = ldcs_pf(&sg[j2]),
               d2 = ldcs_pf(&mp[j2]), e2 = ldcs_pf(&yt[j2]);
        float4 a3 = ldcs_pf(&w[j3]),  b3 = ldcs_pf(&mu[j3]),  c3 = ldcs_pf(&sg[j3]),
               d3 = ldcs_pf(&mp[j3]), e3 = ldcs_pf(&yt[j3]);

        float s = (quad(a0, b0, c0, d0, e0, inv_sp) + quad(a1, b1, c1, d1, e1, inv_sp))
                + (quad(a2, b2, c2, d2, e2, inv_sp) + quad(a3, b3, c3, d3, e3, inv_sp));
        accfx += __double2ll_rn((double)s * FXSCALE);   // order-independent

        c = __shfl_sync(0xFFFFFFFFu, cn, 0);
    }

    // ---- warp reduce (int64) + global finalize
    #pragma unroll
    for (int off = 16; off > 0; off >>= 1)
        accfx += __shfl_xor_sync(0xFFFFFFFFu, accfx, off);

    if (lane == 0) {
        atomicAdd((unsigned long long*)&g_sum, (unsigned long long)accfx);
        __threadfence();
        unsigned nwarps = gridDim.x * (blockDim.x >> 5);
        unsigned t = atomicAdd(&g_done, 1u);
        if (t == nwarps - 1) {
            long long tot = (long long)atomicAdd((unsigned long long*)&g_sum, 0ull);
            double total = (double)tot / FXSCALE;
            double sp = (double)(*sp_ptr);
            double cc = (double)n_batch * (log(sp) + HALF_LOG_2PI);
            out[0] = (float)(total + cc);
            g_sum    = 0;   // reset for next graph replay
            g_done   = 0;
            g_ticket = 0;
        }
    }
}

extern "C" void kernel_launch(void* const* d_in, const int* in_sizes, int n_in,
                              void* d_out, int out_size) {
    // metadata order: noisy_weights, mu_weights, sigma_weights,
    //                 mu_prediction, sigma_prediction (scalar), y_true
    const float4* w  = (const float4*)d_in[0];
    const float4* mu = (const float4*)d_in[1];
    const float4* sg = (const float4*)d_in[2];
    const float4* mp = (const float4*)d_in[3];
    const float*  sp = (const float*) d_in[4];
    const float4* yt = (const float4*)d_in[5];

    int n  = in_sizes[0];      // 2^24, divisible by 4
    int n4 = n >> 2;

    // 72% static, 28% stolen in 128-float4 warp chunks (chunk-aligned split)
    int S       = (int)(((long long)n4 * 72 / 100) & ~127LL);
    int nchunks = (n4 - S) >> 7;
    S = n4 - (nchunks << 7);   // fold any non-multiple-of-128 leftover into static

    fused_loss_kernel<<<BLOCKS, THREADS>>>(w, mu, sg, mp, yt, sp,
                                           (float*)d_out, S, nchunks, in_sizes[5]);
}

// round 10
// speedup vs baseline: 1.0110x; 1.0110x over previous
#include <cuda_runtime.h>
#include <cuda_bf16.h>
#include <math.h>

// total = sum_i [ 0.5*(w^2 - ((w-mu)/sig)^2) - log(sig) ]   (weights)
//       + sum_j [ 0.5*((y-mup)/sp)^2 ]                       (likelihood, negated)
//       + B * (log(sp) + HALF_LOG_2PI)                       (closed-form constant)
//
// Hybrid schedule: 84% fully-pipelined static grid-stride + 16% warp-level
// chunk stealing. All partials in int64 fixed-point -> order-independent,
// bit-deterministic across graph replays.

#define HALF_LOG_2PI 0.9189385332046727
#define LN2F 0.6931471805599453f

static constexpr int    BLOCKS  = 296;   // 148 SMs x 2 resident blocks, single wave
static constexpr int    THREADS = 256;
static constexpr double FXSCALE = 4194304.0;   // 2^22

__device__ long long    g_sum    = 0;
__device__ unsigned int g_ticket = 0;
__device__ unsigned int g_done   = 0;

__device__ __forceinline__ float frcp_fast(float x) {
    float r;
    asm("rcp.approx.ftz.f32 %0, %1;" : "=f"(r) : "f"(x));
    return r;
}

__device__ __forceinline__ float4 ldcs_pf(const float4* p) {
    float4 v;
    asm volatile("ld.global.cs.L2::256B.v4.f32 {%0,%1,%2,%3}, [%4];"
                 : "=f"(v.x), "=f"(v.y), "=f"(v.z), "=f"(v.w) : "l"(p));
    return v;
}

__device__ __forceinline__ float quad(const float4& a, const float4& b,
                                      const float4& c, const float4& d,
                                      const float4& e, float inv_sp) {
    float zx = (a.x - b.x) * frcp_fast(c.x);
    float zy = (a.y - b.y) * frcp_fast(c.y);
    float zz = (a.z - b.z) * frcp_fast(c.z);
    float zw = (a.w - b.w) * frcp_fast(c.w);
    float ux = (e.x - d.x) * inv_sp;
    float uy = (e.y - d.y) * inv_sp;
    float uz = (e.z - d.z) * inv_sp;
    float uw = (e.w - d.w) * inv_sp;

    float sq = (a.x * a.x - zx * zx) + (a.y * a.y - zy * zy)
             + (a.z * a.z - zz * zz) + (a.w * a.w - zw * zw)
             + (ux * ux + uy * uy) + (uz * uz + uw * uw);

    float prod = (c.x * c.y) * (c.z * c.w);   // grouped log: 1 MUFU per 4 sigmas
    return 0.5f * sq - LN2F * __log2f(prod);
}

__global__ __launch_bounds__(THREADS, 2)
void fused_loss_kernel(const float4* __restrict__ w,
                       const float4* __restrict__ mu,
                       const float4* __restrict__ sg,
                       const float4* __restrict__ mp,
                       const float4* __restrict__ yt,
                       const float*  __restrict__ sp_ptr,
                       float* __restrict__ out,
                       int S, int nchunks, int n_batch) {
    const float inv_sp = frcp_fast(*sp_ptr);
    const int stride  = gridDim.x * blockDim.x;
    const int stride4 = stride * 4;
    const int lane    = threadIdx.x & 31;

    // ---- static region [0, S): fully pipelined, 4x unroll, 20 LDG front-batched
    float acc0 = 0.0f, acc1 = 0.0f, acc2 = 0.0f, acc3 = 0.0f;
    int i = blockIdx.x * blockDim.x + threadIdx.x;
    for (; i + 3 * stride < S; i += stride4) {
        int i1 = i + stride, i2 = i + 2 * stride, i3 = i + 3 * stride;
        float4 a0 = ldcs_pf(&w[i]),  b0 = ldcs_pf(&mu[i]),  c0 = ldcs_pf(&sg[i]),
               d0 = ldcs_pf(&mp[i]), e0 = ldcs_pf(&yt[i]);
        float4 a1 = ldcs_pf(&w[i1]), b1 = ldcs_pf(&mu[i1]), c1 = ldcs_pf(&sg[i1]),
               d1 = ldcs_pf(&mp[i1]), e1 = ldcs_pf(&yt[i1]);
        float4 a2 = ldcs_pf(&w[i2]), b2 = ldcs_pf(&mu[i2]), c2 = ldcs_pf(&sg[i2]),
               d2 = ldcs_pf(&mp[i2]), e2 = ldcs_pf(&yt[i2]);
        float4 a3 = ldcs_pf(&w[i3]), b3 = ldcs_pf(&mu[i3]), c3 = ldcs_pf(&sg[i3]),
               d3 = ldcs_pf(&mp[i3]), e3 = ldcs_pf(&yt[i3]);
        acc0 += quad(a0, b0, c0, d0, e0, inv_sp);
        acc1 += quad(a1, b1, c1, d1, e1, inv_sp);
        acc2 += quad(a2, b2, c2, d2, e2, inv_sp);
        acc3 += quad(a3, b3, c3, d3, e3, inv_sp);
    }
    for (; i < S; i += stride) {
        float4 a = ldcs_pf(&w[i]), b = ldcs_pf(&mu[i]), c = ldcs_pf(&sg[i]),
               d = ldcs_pf(&mp[i]), e = ldcs_pf(&yt[i]);
        acc0 += quad(a, b, c, d, e, inv_sp);
    }

    long long accfx =
        __double2ll_rn((double)((acc0 + acc1) + (acc2 + acc3)) * FXSCALE);

    // ---- dynamic tail [S, S + nchunks*128): warp-level chunk stealing
    unsigned c = 0;
    if (lane == 0) c = atomicAdd(&g_ticket, 1u);
    c = __shfl_sync(0xFFFFFFFFu, c, 0);
    while (c < (unsigned)nchunks) {
        unsigned cn = 0;
        if (lane == 0) cn = atomicAdd(&g_ticket, 1u);   // prefetch next ticket

        int j0 = S + ((int)c << 7) + lane;
        int j1 = j0 + 32, j2 = j0 + 64, j3 = j0 + 96;
        float4 a0 = ldcs_pf(&w[j0]),  b0 = ldcs_pf(&mu[j0]),  c0 = ldcs_pf(&sg[j0]),
               d0 = ldcs_pf(&mp[j0]), e0 = ldcs_pf(&yt[j0]);
        float4 a1 = ldcs_pf(&w[j1]),  b1 = ldcs_pf(&mu[j1]),  c1 = ldcs_pf(&sg[j1]),
               d1 = ldcs_pf(&mp[j1]), e1 = ldcs_pf(&yt[j1]);
        float4 a2 = ldcs_pf(&w[j2]),  b2 = ldcs_pf(&mu[j2]),  c2 = ldcs_pf(&sg[j2]),
               d2 = ldcs_pf(&mp[j2]), e2 = ldcs_pf(&yt[j2]);
        float4 a3 = ldcs_pf(&w[j3]),  b3 = ldcs_pf(&mu[j3]),  c3 = ldcs_pf(&sg[j3]),
               d3 = ldcs_pf(&mp[j3]), e3 = ldcs_pf(&yt[j3]);

        float s = (quad(a0, b0, c0, d0, e0, inv_sp) + quad(a1, b1, c1, d1, e1, inv_sp))
                + (quad(a2, b2, c2, d2, e2, inv_sp) + quad(a3, b3, c3, d3, e3, inv_sp));
        accfx += __double2ll_rn((double)s * FXSCALE);   // order-independent

        c = __shfl_sync(0xFFFFFFFFu, cn, 0);
    }

    // ---- warp reduce (int64) + global finalize
    #pragma unroll
    for (int off = 16; off > 0; off >>= 1)
        accfx += __shfl_xor_sync(0xFFFFFFFFu, accfx, off);

    if (lane == 0) {
        atomicAdd((unsigned long long*)&g_sum, (unsigned long long)accfx);
        __threadfence();
        unsigned nwarps = gridDim.x * (blockDim.x >> 5);
        unsigned t = atomicAdd(&g_done, 1u);
        if (t == nwarps - 1) {
            // all prior g_sum adds are ordered before their g_done increments
            // (threadfence), so a plain volatile read suffices here
            long long tot = *(volatile long long*)&g_sum;
            double total = (double)tot / FXSCALE;
            double sp = (double)(*sp_ptr);
            double cc = (double)n_batch * (log(sp) + HALF_LOG_2PI);
            out[0] = (float)(total + cc);
            g_sum    = 0;   // reset for next graph replay
            g_done   = 0;
            g_ticket = 0;
        }
    }
}

extern "C" void kernel_launch(void* const* d_in, const int* in_sizes, int n_in,
                              void* d_out, int out_size) {
    // metadata order: noisy_weights, mu_weights, sigma_weights,
    //                 mu_prediction, sigma_prediction (scalar), y_true
    const float4* w  = (const float4*)d_in[0];
    const float4* mu = (const float4*)d_in[1];
    const float4* sg = (const float4*)d_in[2];
    const float4* mp = (const float4*)d_in[3];
    const float*  sp = (const float*) d_in[4];
    const float4* yt = (const float4*)d_in[5];

    int n  = in_sizes[0];      // 2^24, divisible by 4
    int n4 = n >> 2;

    // 84% static, 16% stolen in 128-float4 warp chunks (chunk-aligned split)
    int S       = (int)(((long long)n4 * 84 / 100) & ~127LL);
    int nchunks = (n4 - S) >> 7;
    S = n4 - (nchunks << 7);   // fold any non-multiple-of-128 leftover into static

    fused_loss_kernel<<<BLOCKS, THREADS>>>(w, mu, sg, mp, yt, sp,
                                           (float*)d_out, S, nchunks, in_sizes[5]);
}

// round 11
// speedup vs baseline: 1.0375x; 1.0262x over previous
#include <cuda_runtime.h>
#include <cuda_bf16.h>
#include <math.h>

// total = sum_i [ 0.5*(w^2 - ((w-mu)/sig)^2) - log(sig) ]   (weights)
//       + sum_j [ 0.5*((y-mup)/sp)^2 ]                       (likelihood, negated)
//       + B * (log(sp) + HALF_LOG_2PI)                       (closed-form constant)
//
// 256-bit (v8.f32) streaming loads -- sm_100+ LDG.E.256 -- halve LSU request
// count vs float4. Pure static grid-stride (best-measured schedule), 2x unroll,
// 10 LDG.256 front-batched per iteration. Deterministic fixed-point finalize.

#define HALF_LOG_2PI 0.9189385332046727
#define LN2F 0.6931471805599453f

static constexpr int    BLOCKS  = 296;   // 148 SMs x 2 resident blocks, single wave
static constexpr int    THREADS = 256;
static constexpr double FXSCALE = 4194304.0;   // 2^22

__device__ long long    g_sum   = 0;
__device__ unsigned int g_count = 0;

struct f8 { float4 lo, hi; };

__device__ __forceinline__ float frcp_fast(float x) {
    float r;
    asm("rcp.approx.ftz.f32 %0, %1;" : "=f"(r) : "f"(x));
    return r;
}

// 256-bit streaming load (sm_100+)
__device__ __forceinline__ f8 ldcs_v8(const float* p) {
    f8 v;
    asm volatile("ld.global.cs.v8.f32 {%0,%1,%2,%3,%4,%5,%6,%7}, [%8];"
                 : "=f"(v.lo.x), "=f"(v.lo.y), "=f"(v.lo.z), "=f"(v.lo.w),
                   "=f"(v.hi.x), "=f"(v.hi.y), "=f"(v.hi.z), "=f"(v.hi.w)
                 : "l"(p));
    return v;
}

__device__ __forceinline__ float quad(const float4& a, const float4& b,
                                      const float4& c, const float4& d,
                                      const float4& e, float inv_sp) {
    float zx = (a.x - b.x) * frcp_fast(c.x);
    float zy = (a.y - b.y) * frcp_fast(c.y);
    float zz = (a.z - b.z) * frcp_fast(c.z);
    float zw = (a.w - b.w) * frcp_fast(c.w);
    float ux = (e.x - d.x) * inv_sp;
    float uy = (e.y - d.y) * inv_sp;
    float uz = (e.z - d.z) * inv_sp;
    float uw = (e.w - d.w) * inv_sp;

    float sq = (a.x * a.x - zx * zx) + (a.y * a.y - zy * zy)
             + (a.z * a.z - zz * zz) + (a.w * a.w - zw * zw)
             + (ux * ux + uy * uy) + (uz * uz + uw * uw);

    float prod = (c.x * c.y) * (c.z * c.w);   // grouped log: 1 MUFU per 4 sigmas
    return 0.5f * sq - LN2F * __log2f(prod);
}

__device__ __forceinline__ float oct(const f8& a, const f8& b, const f8& c,
                                     const f8& d, const f8& e, float inv_sp) {
    return quad(a.lo, b.lo, c.lo, d.lo, e.lo, inv_sp)
         + quad(a.hi, b.hi, c.hi, d.hi, e.hi, inv_sp);
}

__global__ __launch_bounds__(THREADS, 2)
void fused_loss_kernel(const float* __restrict__ w,
                       const float* __restrict__ mu,
                       const float* __restrict__ sg,
                       const float* __restrict__ mp,
                       const float* __restrict__ yt,
                       const float* __restrict__ sp_ptr,
                       float* __restrict__ out,
                       int n8, int n_batch) {
    const float inv_sp = frcp_fast(*sp_ptr);
    const int stride  = gridDim.x * blockDim.x;   // in float8 units
    const int stride2 = stride * 2;

    float acc0 = 0.0f, acc1 = 0.0f;
    int i = blockIdx.x * blockDim.x + threadIdx.x;

    // 2x unroll, 10 LDG.256 front-batched (10 KB per warp-iteration)
    for (; i + stride < n8; i += stride2) {
        long o0 = (long)i << 3;
        long o1 = (long)(i + stride) << 3;
        f8 a0 = ldcs_v8(w  + o0), b0 = ldcs_v8(mu + o0), c0 = ldcs_v8(sg + o0),
           d0 = ldcs_v8(mp + o0), e0 = ldcs_v8(yt + o0);
        f8 a1 = ldcs_v8(w  + o1), b1 = ldcs_v8(mu + o1), c1 = ldcs_v8(sg + o1),
           d1 = ldcs_v8(mp + o1), e1 = ldcs_v8(yt + o1);
        acc0 += oct(a0, b0, c0, d0, e0, inv_sp);
        acc1 += oct(a1, b1, c1, d1, e1, inv_sp);
    }
    for (; i < n8; i += stride) {
        long o = (long)i << 3;
        f8 a = ldcs_v8(w + o), b = ldcs_v8(mu + o), c = ldcs_v8(sg + o),
           d = ldcs_v8(mp + o), e = ldcs_v8(yt + o);
        acc0 += oct(a, b, c, d, e, inv_sp);
    }

    float acc = acc0 + acc1;

    // warp reduce
    #pragma unroll
    for (int off = 16; off > 0; off >>= 1)
        acc += __shfl_xor_sync(0xFFFFFFFFu, acc, off);

    __shared__ double s_warp[THREADS / 32];
    int lane = threadIdx.x & 31;
    int wid  = threadIdx.x >> 5;
    if (lane == 0) s_warp[wid] = (double)acc;
    __syncthreads();

    if (threadIdx.x == 0) {
        double bsum = 0.0;
        #pragma unroll
        for (int k = 0; k < THREADS / 32; k++) bsum += s_warp[k];

        // fixed-point: integer adds are order-independent -> deterministic
        long long fx = __double2ll_rn(bsum * FXSCALE);
        atomicAdd((unsigned long long*)&g_sum, (unsigned long long)fx);
        __threadfence();
        unsigned int ticket = atomicAdd(&g_count, 1u);
        if (ticket == (unsigned int)(gridDim.x - 1)) {
            long long tot = *(volatile long long*)&g_sum;
            double total = (double)tot / FXSCALE;
            double sp = (double)(*sp_ptr);
            double cc = (double)n_batch * (log(sp) + HALF_LOG_2PI);
            out[0] = (float)(total + cc);
            g_sum   = 0;   // reset for next graph replay
            g_count = 0;
        }
    }
}

extern "C" void kernel_launch(void* const* d_in, const int* in_sizes, int n_in,
                              void* d_out, int out_size) {
    // metadata order: noisy_weights, mu_weights, sigma_weights,
    //                 mu_prediction, sigma_prediction (scalar), y_true
    const float* w  = (const float*)d_in[0];
    const float* mu = (const float*)d_in[1];
    const float* sg = (const float*)d_in[2];
    const float* mp = (const float*)d_in[3];
    const float* sp = (const float*)d_in[4];
    const float* yt = (const float*)d_in[5];

    int n  = in_sizes[0];      // 2^24, divisible by 8
    int n8 = n >> 3;

    fused_loss_kernel<<<BLOCKS, THREADS>>>(w, mu, sg, mp, yt, sp,
                                           (float*)d_out, n8, in_sizes[5]);
}